// round 1
// baseline (speedup 1.0000x reference)
#include <cuda_runtime.h>
#include <cstdint>

#define C_    80
#define H_    32
#define W_    88
#define HW_   (H_ * W_)
#define NXg   128
#define NYg   128
#define NZg   16
#define NPTS  (NXg * NYg * NZg)   // 262144 points per batch
#define PPT   4                   // points per thread (float4 store)
#define TPB   256

__global__ __launch_bounds__(TPB) void fvt_kernel(
    const float* __restrict__ img,     // (B, C, H, W)
    const float* __restrict__ intrin,  // (B, 1, 4, 4)
    const float* __restrict__ extrin,  // (B, 1, 4, 4)
    const float* __restrict__ bda,     // (B, 4, 4)
    float* __restrict__ out)           // (B, C, NX, NY, NZ)
{
    __shared__ float s_bda[16];
    __shared__ float s_proj[12];

    const int b = blockIdx.y;

    if (threadIdx.x < 16) s_bda[threadIdx.x] = bda[b * 16 + threadIdx.x];
    if (threadIdx.x < 12) {
        // proj[i][j] = sum_k (intrin[i][k] * scale_i) * extrin[k][j], i<3, j<4
        const int i = threadIdx.x >> 2;
        const int j = threadIdx.x & 3;
        const float sc = (i < 2) ? 0.125f : 1.0f;   // 1/DOWNSAMPLE on rows 0,1
        const float* IN = intrin + b * 16;
        const float* EX = extrin + b * 16;
        float acc = 0.0f;
        #pragma unroll
        for (int k = 0; k < 3; k++)
            acc += (IN[i * 4 + k] * sc) * EX[k * 4 + j];
        s_proj[threadIdx.x] = acc;
    }
    __syncthreads();

    const int n0 = (blockIdx.x * TPB + threadIdx.x) * PPT;

    int   idx[PPT][4];
    float w  [PPT][4];
    bool  any = false;

    #pragma unroll
    for (int p = 0; p < PPT; p++) {
        const int n  = n0 + p;
        const int iz = n & (NZg - 1);
        const int t  = n >> 4;
        const int iy = t & (NYg - 1);
        const int ix = t >> 7;

        // match jnp: bound[0] + arange*step  (mul then add, no FMA contraction)
        const float px = __fadd_rn(__fmul_rn((float)ix, 0.8f), -51.2f);
        const float py = __fadd_rn(__fmul_rn((float)iy, 0.8f), -51.2f);
        const float pz = __fadd_rn(__fmul_rn((float)iz, 0.5f), -5.0f);

        // q = bda @ [px,py,pz,1]
        const float q0 = s_bda[ 0]*px + s_bda[ 1]*py + s_bda[ 2]*pz + s_bda[ 3];
        const float q1 = s_bda[ 4]*px + s_bda[ 5]*py + s_bda[ 6]*pz + s_bda[ 7];
        const float q2 = s_bda[ 8]*px + s_bda[ 9]*py + s_bda[10]*pz + s_bda[11];
        const float q3 = s_bda[12]*px + s_bda[13]*py + s_bda[14]*pz + s_bda[15];

        // pix = proj(3x4) @ q
        const float p0 = s_proj[0]*q0 + s_proj[1]*q1 + s_proj[ 2]*q2 + s_proj[ 3]*q3;
        const float p1 = s_proj[4]*q0 + s_proj[5]*q1 + s_proj[ 6]*q2 + s_proj[ 7]*q3;
        const float p2 = s_proj[8]*q0 + s_proj[9]*q1 + s_proj[10]*q2 + s_proj[11]*q3;

        const float u = __fdiv_rn(p0, p2);
        const float v = __fdiv_rn(p1, p2);

        // un = u/W*2-1 ; x = (un+1)*0.5*(W-1)   (replicate op order)
        const float un = __fadd_rn(__fmul_rn(__fdiv_rn(u, 88.0f), 2.0f), -1.0f);
        const float vn = __fadd_rn(__fmul_rn(__fdiv_rn(v, 32.0f), 2.0f), -1.0f);
        float x = __fmul_rn(__fmul_rn(__fadd_rn(un, 1.0f), 0.5f), 87.0f);
        float y = __fmul_rn(__fmul_rn(__fadd_rn(vn, 1.0f), 0.5f), 31.0f);

        // finite check via exponent bits (robust under any fast-math setting)
        const unsigned ex = __float_as_uint(x) & 0x7f800000u;
        const unsigned ey = __float_as_uint(y) & 0x7f800000u;
        if (ex == 0x7f800000u || ey == 0x7f800000u) { x = -10.0f; y = -10.0f; }

        const float x0f = floorf(x), y0f = floorf(y);
        const float x1f = x0f + 1.0f, y1f = y0f + 1.0f;
        const float wx1 = x - x0f, wx0 = 1.0f - wx1;
        const float wy1 = y - y0f, wy0 = 1.0f - wy1;

        const bool vx0 = (x0f >= 0.0f) && (x0f < 88.0f);
        const bool vx1 = (x1f >= 0.0f) && (x1f < 88.0f);
        const bool vy0 = (y0f >= 0.0f) && (y0f < 32.0f);
        const bool vy1 = (y1f >= 0.0f) && (y1f < 32.0f);

        // clip float, then cast (matches jnp.clip(...).astype(int32))
        const int ix0 = (int)fminf(fmaxf(x0f, 0.0f), 87.0f);
        const int ix1 = (int)fminf(fmaxf(x1f, 0.0f), 87.0f);
        const int iy0 = (int)fminf(fmaxf(y0f, 0.0f), 31.0f);
        const int iy1 = (int)fminf(fmaxf(y1f, 0.0f), 31.0f);

        idx[p][0] = iy0 * W_ + ix0;
        idx[p][1] = iy0 * W_ + ix1;
        idx[p][2] = iy1 * W_ + ix0;
        idx[p][3] = iy1 * W_ + ix1;

        w[p][0] = (vx0 && vy0) ? wx0 * wy0 : 0.0f;
        w[p][1] = (vx1 && vy0) ? wx1 * wy0 : 0.0f;
        w[p][2] = (vx0 && vy1) ? wx0 * wy1 : 0.0f;
        w[p][3] = (vx1 && vy1) ? wx1 * wy1 : 0.0f;

        any = any || ((vx0 || vx1) && (vy0 || vy1));
    }

    const float* fb = img + (size_t)b * C_ * HW_;
    float4* ob = (float4*)(out + (size_t)b * C_ * NPTS + n0);
    const int stride4 = NPTS / 4;   // float4 stride between channels

    if (!any) {
        const float4 z = make_float4(0.0f, 0.0f, 0.0f, 0.0f);
        #pragma unroll 8
        for (int c = 0; c < C_; c++)
            __stcs(ob + c * stride4, z);
    } else {
        #pragma unroll 2
        for (int c = 0; c < C_; c++) {
            const float* fc = fb + c * HW_;
            float4 r;
            r.x = w[0][0]*__ldg(fc + idx[0][0]) + w[0][1]*__ldg(fc + idx[0][1])
                + w[0][2]*__ldg(fc + idx[0][2]) + w[0][3]*__ldg(fc + idx[0][3]);
            r.y = w[1][0]*__ldg(fc + idx[1][0]) + w[1][1]*__ldg(fc + idx[1][1])
                + w[1][2]*__ldg(fc + idx[1][2]) + w[1][3]*__ldg(fc + idx[1][3]);
            r.z = w[2][0]*__ldg(fc + idx[2][0]) + w[2][1]*__ldg(fc + idx[2][1])
                + w[2][2]*__ldg(fc + idx[2][2]) + w[2][3]*__ldg(fc + idx[2][3]);
            r.w = w[3][0]*__ldg(fc + idx[3][0]) + w[3][1]*__ldg(fc + idx[3][1])
                + w[3][2]*__ldg(fc + idx[3][2]) + w[3][3]*__ldg(fc + idx[3][3]);
            __stcs(ob + c * stride4, r);
        }
    }
}

extern "C" void kernel_launch(void* const* d_in, const int* in_sizes, int n_in,
                              void* d_out, int out_size)
{
    (void)in_sizes; (void)n_in; (void)out_size;
    const float* img    = (const float*)d_in[0];
    const float* intrin = (const float*)d_in[1];
    const float* extrin = (const float*)d_in[2];
    const float* bda    = (const float*)d_in[3];
    float* out          = (float*)d_out;

    dim3 grid(NPTS / (TPB * PPT), 2);   // 256 blocks/batch, B=2
    fvt_kernel<<<grid, TPB>>>(img, intrin, extrin, bda, out);
}

// round 2
// speedup vs baseline: 1.3023x; 1.3023x over previous
#include <cuda_runtime.h>
#include <cstdint>

#define C_    80
#define H_    32
#define W_    88
#define HW_   (H_ * W_)          // 2816
#define NXg   128
#define NYg   128
#define NZg   16
#define NPTS  (NXg * NYg * NZg)  // 262144 points per batch
#define TPB   256
#define NCH4  (C_ / 4)           // 20 channel chunks

// (B, H*W, C) channel-last copy of the feature map. 2*2816*80 floats = 1.8 MB.
__device__ float g_imgT[2 * HW_ * C_];

// ---------------------------------------------------------------------------
// Pass 1: (B, C, HW) -> (B, HW, C) tiled transpose
// ---------------------------------------------------------------------------
__global__ void fvt_transpose(const float* __restrict__ img)
{
    __shared__ float tile[32][33];
    const int b   = blockIdx.z;
    const int hw0 = blockIdx.x * 32;
    const int c0  = blockIdx.y * 32;
    const int tx  = threadIdx.x;      // 0..31
    const int ty  = threadIdx.y;      // 0..7

    #pragma unroll
    for (int i = 0; i < 4; i++) {
        const int c  = c0 + ty + i * 8;
        const int hw = hw0 + tx;
        if (c < C_ && hw < HW_)
            tile[ty + i * 8][tx] = img[((size_t)b * C_ + c) * HW_ + hw];
    }
    __syncthreads();
    #pragma unroll
    for (int i = 0; i < 4; i++) {
        const int hw = hw0 + ty + i * 8;
        const int c  = c0 + tx;
        if (hw < HW_ && c < C_)
            g_imgT[((size_t)b * HW_ + hw) * C_ + c] = tile[tx][ty + i * 8];
    }
}

// ---------------------------------------------------------------------------
// Pass 2: project + bilinear gather (channel-vectorized) + streamed store
// ---------------------------------------------------------------------------
__global__ __launch_bounds__(TPB, 4) void fvt_kernel(
    const float* __restrict__ intrin,  // (B, 1, 4, 4)
    const float* __restrict__ extrin,  // (B, 1, 4, 4)
    const float* __restrict__ bda,     // (B, 4, 4)
    float* __restrict__ out)           // (B, C, NX, NY, NZ)
{
    __shared__ float s_bda[16];
    __shared__ float s_proj[12];

    const int b = blockIdx.y;

    if (threadIdx.x < 16) s_bda[threadIdx.x] = bda[b * 16 + threadIdx.x];
    if (threadIdx.x < 12) {
        // proj[i][j] = sum_k (intrin[i][k] * scale_i) * extrin[k][j]
        const int i = threadIdx.x >> 2;
        const int j = threadIdx.x & 3;
        const float sc = (i < 2) ? 0.125f : 1.0f;
        const float* IN = intrin + b * 16;
        const float* EX = extrin + b * 16;
        float acc = 0.0f;
        #pragma unroll
        for (int k = 0; k < 3; k++)
            acc += (IN[i * 4 + k] * sc) * EX[k * 4 + j];
        s_proj[threadIdx.x] = acc;
    }
    __syncthreads();

    const int n  = blockIdx.x * TPB + threadIdx.x;
    const int iz = n & (NZg - 1);
    const int t  = n >> 4;
    const int iy = t & (NYg - 1);
    const int ix = t >> 7;

    // match jnp: bound[0] + arange*step  (mul then add, no FMA contraction)
    const float px = __fadd_rn(__fmul_rn((float)ix, 0.8f), -51.2f);
    const float py = __fadd_rn(__fmul_rn((float)iy, 0.8f), -51.2f);
    const float pz = __fadd_rn(__fmul_rn((float)iz, 0.5f), -5.0f);

    // q = bda @ [px,py,pz,1]
    const float q0 = s_bda[ 0]*px + s_bda[ 1]*py + s_bda[ 2]*pz + s_bda[ 3];
    const float q1 = s_bda[ 4]*px + s_bda[ 5]*py + s_bda[ 6]*pz + s_bda[ 7];
    const float q2 = s_bda[ 8]*px + s_bda[ 9]*py + s_bda[10]*pz + s_bda[11];
    const float q3 = s_bda[12]*px + s_bda[13]*py + s_bda[14]*pz + s_bda[15];

    // pix = proj(3x4) @ q
    const float p0 = s_proj[0]*q0 + s_proj[1]*q1 + s_proj[ 2]*q2 + s_proj[ 3]*q3;
    const float p1 = s_proj[4]*q0 + s_proj[5]*q1 + s_proj[ 6]*q2 + s_proj[ 7]*q3;
    const float p2 = s_proj[8]*q0 + s_proj[9]*q1 + s_proj[10]*q2 + s_proj[11]*q3;

    const float u = __fdiv_rn(p0, p2);
    const float v = __fdiv_rn(p1, p2);

    // un = u/W*2-1 ; x = (un+1)*0.5*(W-1)   (replicate reference op order)
    const float un = __fadd_rn(__fmul_rn(__fdiv_rn(u, 88.0f), 2.0f), -1.0f);
    const float vn = __fadd_rn(__fmul_rn(__fdiv_rn(v, 32.0f), 2.0f), -1.0f);
    float x = __fmul_rn(__fmul_rn(__fadd_rn(un, 1.0f), 0.5f), 87.0f);
    float y = __fmul_rn(__fmul_rn(__fadd_rn(vn, 1.0f), 0.5f), 31.0f);

    // finite check via exponent bits (robust under any fast-math setting)
    const unsigned exb = __float_as_uint(x) & 0x7f800000u;
    const unsigned eyb = __float_as_uint(y) & 0x7f800000u;
    if (exb == 0x7f800000u || eyb == 0x7f800000u) { x = -10.0f; y = -10.0f; }

    const float x0f = floorf(x), y0f = floorf(y);
    const float x1f = x0f + 1.0f, y1f = y0f + 1.0f;
    const float wx1 = x - x0f, wx0 = 1.0f - wx1;
    const float wy1 = y - y0f, wy0 = 1.0f - wy1;

    const bool vx0 = (x0f >= 0.0f) && (x0f < 88.0f);
    const bool vx1 = (x1f >= 0.0f) && (x1f < 88.0f);
    const bool vy0 = (y0f >= 0.0f) && (y0f < 32.0f);
    const bool vy1 = (y1f >= 0.0f) && (y1f < 32.0f);

    const int ix0 = (int)fminf(fmaxf(x0f, 0.0f), 87.0f);
    const int ix1 = (int)fminf(fmaxf(x1f, 0.0f), 87.0f);
    const int iy0 = (int)fminf(fmaxf(y0f, 0.0f), 31.0f);
    const int iy1 = (int)fminf(fmaxf(y1f, 0.0f), 31.0f);

    const float w00 = (vx0 && vy0) ? wx0 * wy0 : 0.0f;
    const float w10 = (vx1 && vy0) ? wx1 * wy0 : 0.0f;
    const float w01 = (vx0 && vy1) ? wx0 * wy1 : 0.0f;
    const float w11 = (vx1 && vy1) ? wx1 * wy1 : 0.0f;

    const bool any = (vx0 || vx1) && (vy0 || vy1);

    const float* rowbase = g_imgT + (size_t)b * HW_ * C_;
    const float4* pc00 = (const float4*)(rowbase + (size_t)(iy0 * W_ + ix0) * C_);
    const float4* pc10 = (const float4*)(rowbase + (size_t)(iy0 * W_ + ix1) * C_);
    const float4* pc01 = (const float4*)(rowbase + (size_t)(iy1 * W_ + ix0) * C_);
    const float4* pc11 = (const float4*)(rowbase + (size_t)(iy1 * W_ + ix1) * C_);

    float* ob = out + (size_t)b * C_ * NPTS + n;

    if (any) {
        #pragma unroll 5
        for (int ch = 0; ch < NCH4; ch++) {
            const float4 a = __ldg(pc00 + ch);
            const float4 bq = __ldg(pc10 + ch);
            const float4 cq = __ldg(pc01 + ch);
            const float4 dq = __ldg(pc11 + ch);
            float4 r;
            r.x = w00*a.x + w10*bq.x + w01*cq.x + w11*dq.x;
            r.y = w00*a.y + w10*bq.y + w01*cq.y + w11*dq.y;
            r.z = w00*a.z + w10*bq.z + w01*cq.z + w11*dq.z;
            r.w = w00*a.w + w10*bq.w + w01*cq.w + w11*dq.w;
            float* o = ob + (size_t)(ch * 4) * NPTS;
            __stcs(o,            r.x);
            __stcs(o +     NPTS, r.y);
            __stcs(o + 2 * NPTS, r.z);
            __stcs(o + 3 * NPTS, r.w);
        }
    } else {
        #pragma unroll 5
        for (int ch = 0; ch < NCH4; ch++) {
            float* o = ob + (size_t)(ch * 4) * NPTS;
            __stcs(o,            0.0f);
            __stcs(o +     NPTS, 0.0f);
            __stcs(o + 2 * NPTS, 0.0f);
            __stcs(o + 3 * NPTS, 0.0f);
        }
    }
}

extern "C" void kernel_launch(void* const* d_in, const int* in_sizes, int n_in,
                              void* d_out, int out_size)
{
    (void)in_sizes; (void)n_in; (void)out_size;
    const float* img    = (const float*)d_in[0];
    const float* intrin = (const float*)d_in[1];
    const float* extrin = (const float*)d_in[2];
    const float* bda    = (const float*)d_in[3];
    float* out          = (float*)d_out;

    dim3 tgrid((HW_ + 31) / 32, (C_ + 31) / 32, 2);
    fvt_transpose<<<tgrid, dim3(32, 8)>>>(img);

    dim3 grid(NPTS / TPB, 2);   // 1024 blocks/batch, B=2
    fvt_kernel<<<grid, TPB>>>(intrin, extrin, bda, out);
}